// round 11
// baseline (speedup 1.0000x reference)
#include <cuda_runtime.h>
#include <cuda_bf16.h>
#include <cstdint>

// Self_Attention: x[B,C,H,W], 1x1-conv projections q,k (D=32), v (C),
// energy = q^T k, softmax over j, out = V @ attn^T, final = gamma*out + x.
// Plain-sm_103 PTX target -> no tcgen05; HMMA (mma.sync) + ldmatrix + cp.async.
// R10: fused_attn warps retiled 16i x 256c -> 32i x 128c: V-fragment LDSM
// traffic per warp halves (crossbar decouples from tensor pipe).
#define BB 4
#define CC_ 256
#define NN 4096
#define DD 32

// Scratch (device globals; no runtime allocation allowed)
__device__ __nv_bfloat16 g_v16[BB][CC_][NN];   // V bf16, 8 MB
__device__ __nv_bfloat16 g_qT[BB][NN][DD];     // q bf16 token-major, 1 MB
__device__ __nv_bfloat16 g_kT[BB][NN][DD];     // k bf16 token-major, 1 MB
__device__ __nv_bfloat16 g_w16[320][CC_];      // W bf16 (q,k,v stacked), 160 KB
__device__ float g_biasf[320];                 // biases (q,k,v stacked)

__device__ __forceinline__ uint32_t smem_u32(const void* p) {
    uint32_t a;
    asm("{ .reg .u64 t; cvta.to.shared.u64 t, %1; cvt.u32.u64 %0, t; }" : "=r"(a) : "l"(p));
    return a;
}

#define CP_ASYNC16(dst, src) \
    asm volatile("cp.async.cg.shared.global [%0], [%1], 16;" :: "r"(dst), "l"(src))
#define CP_COMMIT()  asm volatile("cp.async.commit_group;")
#define CP_WAIT1()   asm volatile("cp.async.wait_group 1;")
#define CP_WAIT0()   asm volatile("cp.async.wait_group 0;")

#define LDMATRIX_X4(r0, r1, r2, r3, addr)                                          \
    asm volatile("ldmatrix.sync.aligned.m8n8.x4.shared.b16 {%0,%1,%2,%3}, [%4];"   \
        : "=r"(r0), "=r"(r1), "=r"(r2), "=r"(r3) : "r"(addr))

#define MMA16816(c, a, b)                                                          \
    asm volatile("mma.sync.aligned.m16n8k16.row.col.f32.bf16.bf16.f32 "            \
        "{%0,%1,%2,%3}, {%4,%5,%6,%7}, {%8,%9}, {%0,%1,%2,%3};"                    \
        : "+f"((c)[0]), "+f"((c)[1]), "+f"((c)[2]), "+f"((c)[3])                   \
        : "r"((a)[0]), "r"((a)[1]), "r"((a)[2]), "r"((a)[3]),                      \
          "r"((b)[0]), "r"((b)[1]))

// ---------------------------------------------------------------------------
// Kernel W: convert weights to bf16 (rows 0-31 q, 32-63 k, 64-319 v) + biases.
// ---------------------------------------------------------------------------
__global__ __launch_bounds__(256) void wconv_kernel(
    const float* __restrict__ wq, const float* __restrict__ bq,
    const float* __restrict__ wk, const float* __restrict__ bk,
    const float* __restrict__ wv, const float* __restrict__ bv)
{
    const int row = blockIdx.x;
    const int t = threadIdx.x;
    const float* src = row < 32 ? wq + row * CC_
                     : row < 64 ? wk + (row - 32) * CC_
                                : wv + (row - 64) * CC_;
    g_w16[row][t] = __float2bfloat16(src[t]);
    if (t == 0)
        g_biasf[row] = row < 32 ? bq[row] : row < 64 ? bk[row - 32] : bv[row - 64];
}

// ---------------------------------------------------------------------------
// Kernel A (HMMA QKV): unchanged from R7.
// ---------------------------------------------------------------------------
#define WROW    528
#define WS_OFF  0
#define XROW    144
#define XS_OFF  168960
#define BI_OFF  (168960 + 18432)
#define SMEM_Q  (168960 + 18432 + 1280)

__global__ __launch_bounds__(256, 1) void qkv_hmma_kernel(
    const float* __restrict__ x)
{
    extern __shared__ char smq[];
    const uint32_t sb = smem_u32(smq);
    const int tid  = threadIdx.x;
    const int wid  = tid >> 5;
    const int lane = tid & 31;
    const int b  = blockIdx.y;
    const int n0 = blockIdx.x * 128;

#pragma unroll
    for (int p = 0; p < 40; p++) {
        int idx = tid + p * 256;
        int row = idx >> 5, seg = idx & 31;
        CP_ASYNC16(sb + WS_OFF + row * WROW + seg * 16, &g_w16[row][seg * 8]);
    }
    if (tid < 80) CP_ASYNC16(sb + BI_OFF + tid * 16, &g_biasf[tid * 4]);
    CP_COMMIT();

    float accQ[8][4];
    float accV[4][8][4];
#pragma unroll
    for (int nt = 0; nt < 8; nt++)
#pragma unroll
        for (int r = 0; r < 4; r++) accQ[nt][r] = 0.f;
#pragma unroll
    for (int mt = 0; mt < 4; mt++)
#pragma unroll
        for (int nt = 0; nt < 8; nt++)
#pragma unroll
            for (int r = 0; r < 4; r++) accV[mt][nt][r] = 0.f;

    const int mw = wid >> 1;
    const int nw = wid & 1;
    const int ntok = tid & 127;
    const int cgrp = (tid >> 7) * 32;

    float xr[32];
    {
        const float* xp = x + ((size_t)(b * CC_ + cgrp)) * NN + n0 + ntok;
#pragma unroll
        for (int q = 0; q < 32; q++) xr[q] = xp[(size_t)q * NN];
    }

    for (int ck = 0; ck < 4; ck++) {
        __syncthreads();
#pragma unroll
        for (int q = 0; q < 16; q++) {
            __nv_bfloat162 pk = __floats2bfloat162_rn(xr[2 * q], xr[2 * q + 1]);
            *(uint32_t*)(smq + XS_OFF + ntok * XROW + (cgrp + 2 * q) * 2) =
                *(uint32_t*)&pk;
        }
        if (ck == 0) CP_WAIT0();
        __syncthreads();

        if (ck < 3) {
            const float* xp = x + ((size_t)(b * CC_ + (ck + 1) * 64 + cgrp)) * NN
                            + n0 + ntok;
#pragma unroll
            for (int q = 0; q < 32; q++) xr[q] = xp[(size_t)q * NN];
        }

        const uint32_t wbase = sb + WS_OFF + ck * 128;
#pragma unroll
        for (int ks = 0; ks < 4; ks++) {
            const int kb = ks * 32;
            uint32_t ax[4];
            {
                uint32_t addr = sb + XS_OFF + (wid * 16 + (lane & 15)) * XROW
                              + kb + ((lane >> 4) << 4);
                LDMATRIX_X4(ax[0], ax[1], ax[2], ax[3], addr);
            }
            uint32_t bw[8][2];
#pragma unroll
            for (int bt = 0; bt < 4; bt++) {
                int row = bt * 16 + ((lane >> 4) << 3) + (lane & 7);
                uint32_t addr = wbase + row * WROW + kb + (((lane >> 3) & 1) << 4);
                uint32_t r0, r1, r2, r3;
                LDMATRIX_X4(r0, r1, r2, r3, addr);
                bw[bt * 2 + 0][0] = r0; bw[bt * 2 + 0][1] = r1;
                bw[bt * 2 + 1][0] = r2; bw[bt * 2 + 1][1] = r3;
            }
#pragma unroll
            for (int nt = 0; nt < 8; nt++) MMA16816(accQ[nt], ax, bw[nt]);

            uint32_t aw[4][4];
#pragma unroll
            for (int mt = 0; mt < 4; mt++) {
                uint32_t addr = wbase + (64 + mw * 64 + mt * 16 + (lane & 15)) * WROW
                              + kb + ((lane >> 4) << 4);
                LDMATRIX_X4(aw[mt][0], aw[mt][1], aw[mt][2], aw[mt][3], addr);
            }
            uint32_t bx[8][2];
#pragma unroll
            for (int bt = 0; bt < 4; bt++) {
                int row = nw * 64 + bt * 16 + ((lane >> 4) << 3) + (lane & 7);
                uint32_t addr = sb + XS_OFF + row * XROW + kb
                              + (((lane >> 3) & 1) << 4);
                uint32_t r0, r1, r2, r3;
                LDMATRIX_X4(r0, r1, r2, r3, addr);
                bx[bt * 2 + 0][0] = r0; bx[bt * 2 + 0][1] = r1;
                bx[bt * 2 + 1][0] = r2; bx[bt * 2 + 1][1] = r3;
            }
#pragma unroll
            for (int mt = 0; mt < 4; mt++)
#pragma unroll
                for (int nt = 0; nt < 8; nt++)
                    MMA16816(accV[mt][nt], aw[mt], bx[nt]);
        }
    }

    const float* biasS = (const float*)(smq + BI_OFF);

    {
        int rq = n0 + wid * 16 + (lane >> 2);
#pragma unroll
        for (int nt = 0; nt < 8; nt++) {
            int r = nt * 8 + (lane & 3) * 2;
            float b0 = biasS[r], b1 = biasS[r + 1];
            __nv_bfloat162 pA = __floats2bfloat162_rn(accQ[nt][0] + b0,
                                                      accQ[nt][1] + b1);
            __nv_bfloat162 pB = __floats2bfloat162_rn(accQ[nt][2] + b0,
                                                      accQ[nt][3] + b1);
            if (nt < 4) {
                *(uint32_t*)&g_qT[b][rq][r]     = *(uint32_t*)&pA;
                *(uint32_t*)&g_qT[b][rq + 8][r] = *(uint32_t*)&pB;
            } else {
                *(uint32_t*)&g_kT[b][rq][r - 32]     = *(uint32_t*)&pA;
                *(uint32_t*)&g_kT[b][rq + 8][r - 32] = *(uint32_t*)&pB;
            }
        }
    }

#pragma unroll
    for (int mt = 0; mt < 4; mt++) {
        int vr = mw * 64 + mt * 16 + (lane >> 2);
        float b0 = biasS[64 + vr], b1 = biasS[64 + vr + 8];
#pragma unroll
        for (int nt = 0; nt < 8; nt++) {
            int col = n0 + nw * 64 + nt * 8 + (lane & 3) * 2;
            __nv_bfloat162 pA = __floats2bfloat162_rn(accV[mt][nt][0] + b0,
                                                      accV[mt][nt][1] + b0);
            __nv_bfloat162 pB = __floats2bfloat162_rn(accV[mt][nt][2] + b1,
                                                      accV[mt][nt][3] + b1);
            *(uint32_t*)&g_v16[b][vr][col]     = *(uint32_t*)&pA;
            *(uint32_t*)&g_v16[b][vr + 8][col] = *(uint32_t*)&pB;
        }
    }
}

// ---------------------------------------------------------------------------
// Kernel F (fused flash attention, HMMA), R10: warp tile 32i x 128c.
//   8 warps: iq=wid&3 -> 32 i-rows, ch=wid>>2 -> 128-c half.
//   Per chunk: S per m-tile (cc liveness 32), exp -> aP[2], then one PV pass
//   over the warp's 128 V rows (V LDSM halved vs R9).
// grid (32 i, 4 b) = 128 CTAs, 256 threads, 94208 B dyn smem.
// ---------------------------------------------------------------------------
#define QS_OFF   0
#define KC_OFF   10240
#define KC_BUF   5120
#define VC_OFF   20480
#define VC_BUF   36864
#define SMEM_F   94208

__global__ __launch_bounds__(256, 1) void fused_attn_kernel(
    const float* __restrict__ x, const float* __restrict__ gamma_p,
    float* __restrict__ out)
{
    extern __shared__ char smem[];
    const uint32_t sb = smem_u32(smem);
    const int tid  = threadIdx.x;
    const int wid  = tid >> 5;
    const int lane = tid & 31;
    const int b  = blockIdx.y;
    const int i0 = blockIdx.x * 128;
    const int iq = wid & 3;     // i-group: rows iq*32 .. +31
    const int ch = wid >> 2;    // c-half: channels ch*128 .. +127

    auto load_chunk = [&](int chunk) {
        const int j0 = chunk * 64;
        {
            int row = tid >> 2, seg = tid & 3;
            CP_ASYNC16(sb + KC_OFF + (chunk & 1) * KC_BUF + row * 80 + seg * 16,
                       &g_kT[b][j0 + row][seg * 8]);
        }
#pragma unroll
        for (int p = 0; p < 8; p++) {
            int idx = tid + p * 256;
            int row = idx >> 3, seg = idx & 7;
            CP_ASYNC16(sb + VC_OFF + (chunk & 1) * VC_BUF + row * 144 + seg * 16,
                       &g_v16[b][row][j0 + seg * 8]);
        }
        CP_COMMIT();
    };

    {
#pragma unroll
        for (int p = 0; p < 2; p++) {
            int idx = tid + p * 256;
            int row = idx >> 2, seg = idx & 3;
            CP_ASYNC16(sb + QS_OFF + row * 80 + seg * 16, &g_qT[b][i0 + row][seg * 8]);
        }
    }
    load_chunk(0);

    float acc[2][16][4];
#pragma unroll
    for (int mt = 0; mt < 2; mt++)
#pragma unroll
        for (int nt = 0; nt < 16; nt++)
#pragma unroll
            for (int r = 0; r < 4; r++) acc[mt][nt][r] = 0.f;

    uint32_t qf[2][2][4];   // [mt][ks]
    float sums[2][2] = {{0.f, 0.f}, {0.f, 0.f}};  // [mt][row-half]

    for (int chunk = 0; chunk < NN / 64; chunk++) {
        if (chunk + 1 < NN / 64) { load_chunk(chunk + 1); CP_WAIT1(); }
        else                     { CP_WAIT0(); }
        __syncthreads();

        if (chunk == 0) {
#pragma unroll
            for (int mt = 0; mt < 2; mt++)
#pragma unroll
                for (int ks = 0; ks < 2; ks++) {
                    uint32_t addr = sb + QS_OFF
                                  + (iq * 32 + mt * 16 + (lane & 15)) * 80
                                  + ks * 32 + ((lane >> 4) << 4);
                    LDMATRIX_X4(qf[mt][ks][0], qf[mt][ks][1],
                                qf[mt][ks][2], qf[mt][ks][3], addr);
                }
        }

        const uint32_t kbuf = sb + KC_OFF + (chunk & 1) * KC_BUF;
        uint32_t aP[2][4][4];

        // ---- S per m-tile (keeps cc liveness at 32 regs) ----
#pragma unroll
        for (int mt = 0; mt < 2; mt++) {
            float cc[8][4];
#pragma unroll
            for (int nt = 0; nt < 8; nt++)
#pragma unroll
                for (int r = 0; r < 4; r++) cc[nt][r] = 0.f;

#pragma unroll
            for (int bt = 0; bt < 4; bt++) {
                const int row = bt * 16 + ((lane >> 4) << 3) + (lane & 7);
                uint32_t k0[4], k1[4];
                LDMATRIX_X4(k0[0], k0[1], k0[2], k0[3],
                            kbuf + row * 80 + (((lane >> 3) & 1) << 4));
                LDMATRIX_X4(k1[0], k1[1], k1[2], k1[3],
                            kbuf + row * 80 + 32 + (((lane >> 3) & 1) << 4));
                uint32_t bfr[2];
                bfr[0] = k0[0]; bfr[1] = k0[1]; MMA16816(cc[bt * 2 + 0], qf[mt][0], bfr);
                bfr[0] = k1[0]; bfr[1] = k1[1]; MMA16816(cc[bt * 2 + 0], qf[mt][1], bfr);
                bfr[0] = k0[2]; bfr[1] = k0[3]; MMA16816(cc[bt * 2 + 1], qf[mt][0], bfr);
                bfr[0] = k1[2]; bfr[1] = k1[3]; MMA16816(cc[bt * 2 + 1], qf[mt][1], bfr);
            }

            // exp + rowsum + repack C-frags -> A-frags of PV mma
#pragma unroll
            for (int nt = 0; nt < 8; nt++) {
                float e0 = __expf(cc[nt][0]);
                float e1 = __expf(cc[nt][1]);
                float e2 = __expf(cc[nt][2]);
                float e3 = __expf(cc[nt][3]);
                sums[mt][0] += e0 + e1;
                sums[mt][1] += e2 + e3;
                __nv_bfloat162 pA = __floats2bfloat162_rn(e0, e1);
                __nv_bfloat162 pB = __floats2bfloat162_rn(e2, e3);
                int kk = nt >> 1;
                if ((nt & 1) == 0) {
                    aP[mt][kk][0] = *(uint32_t*)&pA; aP[mt][kk][1] = *(uint32_t*)&pB;
                } else {
                    aP[mt][kk][2] = *(uint32_t*)&pA; aP[mt][kk][3] = *(uint32_t*)&pB;
                }
            }
        }

        // ---- PV over the warp's 128-c half: V LDSM once per both m-tiles ----
        const uint32_t vbuf = sb + VC_OFF + (chunk & 1) * VC_BUF;
#pragma unroll
        for (int bt = 0; bt < 8; bt++) {
            const int row = ch * 128 + bt * 16 + ((lane >> 4) << 3) + (lane & 7);
            const uint32_t raddr = vbuf + row * 144 + (((lane >> 3) & 1) << 4);
            uint32_t v0[4], v1[4], v2[4], v3[4];
            LDMATRIX_X4(v0[0], v0[1], v0[2], v0[3], raddr);
            LDMATRIX_X4(v1[0], v1[1], v1[2], v1[3], raddr + 32);
            LDMATRIX_X4(v2[0], v2[1], v2[2], v2[3], raddr + 64);
            LDMATRIX_X4(v3[0], v3[1], v3[2], v3[3], raddr + 96);
#pragma unroll
            for (int mt = 0; mt < 2; mt++) {
                uint32_t bfr[2];
                bfr[0] = v0[0]; bfr[1] = v0[1]; MMA16816(acc[mt][bt * 2 + 0], aP[mt][0], bfr);
                bfr[0] = v1[0]; bfr[1] = v1[1]; MMA16816(acc[mt][bt * 2 + 0], aP[mt][1], bfr);
                bfr[0] = v2[0]; bfr[1] = v2[1]; MMA16816(acc[mt][bt * 2 + 0], aP[mt][2], bfr);
                bfr[0] = v3[0]; bfr[1] = v3[1]; MMA16816(acc[mt][bt * 2 + 0], aP[mt][3], bfr);
                bfr[0] = v0[2]; bfr[1] = v0[3]; MMA16816(acc[mt][bt * 2 + 1], aP[mt][0], bfr);
                bfr[0] = v1[2]; bfr[1] = v1[3]; MMA16816(acc[mt][bt * 2 + 1], aP[mt][1], bfr);
                bfr[0] = v2[2]; bfr[1] = v2[3]; MMA16816(acc[mt][bt * 2 + 1], aP[mt][2], bfr);
                bfr[0] = v3[2]; bfr[1] = v3[3]; MMA16816(acc[mt][bt * 2 + 1], aP[mt][3], bfr);
            }
        }
        __syncthreads();
    }

    // ---- rowsum reduce (quad lanes share rows) + gamma-folded inverse ----
    const float gam = gamma_p[0];
    float ig[2][2];
#pragma unroll
    for (int mt = 0; mt < 2; mt++)
#pragma unroll
        for (int h = 0; h < 2; h++) {
            float s = sums[mt][h];
            s += __shfl_xor_sync(0xffffffffu, s, 1);
            s += __shfl_xor_sync(0xffffffffu, s, 2);
            ig[mt][h] = gam / s;
        }

    // ---- epilogue: out = ig*acc + x ----
    const int g2 = lane >> 2;
    const int tg = lane & 3;
#pragma unroll
    for (int mt = 0; mt < 2; mt++) {
        const int irow = i0 + iq * 32 + mt * 16 + g2;
#pragma unroll
        for (int nt = 0; nt < 16; nt++) {
            int c = ch * 128 + nt * 8 + tg * 2;
            size_t o00 = ((size_t)(b * CC_ + c)) * NN + irow;
            size_t o10 = o00 + NN;
            out[o00]     = fmaf(ig[mt][0], acc[mt][nt][0], x[o00]);
            out[o10]     = fmaf(ig[mt][0], acc[mt][nt][1], x[o10]);
            out[o00 + 8] = fmaf(ig[mt][1], acc[mt][nt][2], x[o00 + 8]);
            out[o10 + 8] = fmaf(ig[mt][1], acc[mt][nt][3], x[o10 + 8]);
        }
    }
}

// ---------------------------------------------------------------------------
extern "C" void kernel_launch(void* const* d_in, const int* in_sizes, int n_in,
                              void* d_out, int out_size)
{
    const float* x     = (const float*)d_in[0];
    const float* wq    = (const float*)d_in[1];
    const float* bq    = (const float*)d_in[2];
    const float* wk    = (const float*)d_in[3];
    const float* bk    = (const float*)d_in[4];
    const float* wv    = (const float*)d_in[5];
    const float* bv    = (const float*)d_in[6];
    const float* gamma = (const float*)d_in[7];
    float* out = (float*)d_out;

    cudaFuncSetAttribute(qkv_hmma_kernel,
                         cudaFuncAttributeMaxDynamicSharedMemorySize, SMEM_Q);
    cudaFuncSetAttribute(fused_attn_kernel,
                         cudaFuncAttributeMaxDynamicSharedMemorySize, SMEM_F);

    wconv_kernel<<<dim3(320), 256>>>(wq, bq, wk, bk, wv, bv);
    qkv_hmma_kernel<<<dim3(32, 4), 256, SMEM_Q>>>(x);
    fused_attn_kernel<<<dim3(32, 4), 256, SMEM_F>>>(x, gamma, out);
}

// round 12
// speedup vs baseline: 1.1427x; 1.1427x over previous
#include <cuda_runtime.h>
#include <cuda_bf16.h>
#include <cstdint>

// Self_Attention: x[B,C,H,W], 1x1-conv projections q,k (D=32), v (C),
// energy = q^T k, softmax over j, out = V @ attn^T, final = gamma*out + x.
// Plain-sm_103 PTX target -> no tcgen05; HMMA (mma.sync) + ldmatrix + cp.async.
// R11: revert F to R9 tiling (16i x 256c / warp); triple-buffered K/V with a
// single barrier per chunk + depth-2 prefetch; exp via raw ex2 (log2e folded
// into wq/bq); PV mma pairs interleaved for dependency distance.
#define BB 4
#define CC_ 256
#define NN 4096
#define DD 32

// Scratch (device globals; no runtime allocation allowed)
__device__ __nv_bfloat16 g_v16[BB][CC_][NN];   // V bf16, 8 MB
__device__ __nv_bfloat16 g_qT[BB][NN][DD];     // q*log2e bf16 token-major, 1 MB
__device__ __nv_bfloat16 g_kT[BB][NN][DD];     // k bf16 token-major, 1 MB
__device__ __nv_bfloat16 g_w16[320][CC_];      // W bf16 (q,k,v stacked), 160 KB
__device__ float g_biasf[320];                 // biases (q,k,v stacked)

__device__ __forceinline__ uint32_t smem_u32(const void* p) {
    uint32_t a;
    asm("{ .reg .u64 t; cvta.to.shared.u64 t, %1; cvt.u32.u64 %0, t; }" : "=r"(a) : "l"(p));
    return a;
}

#define CP_ASYNC16(dst, src) \
    asm volatile("cp.async.cg.shared.global [%0], [%1], 16;" :: "r"(dst), "l"(src))
#define CP_COMMIT()  asm volatile("cp.async.commit_group;")
#define CP_WAIT1()   asm volatile("cp.async.wait_group 1;")
#define CP_WAIT0()   asm volatile("cp.async.wait_group 0;")

#define LDMATRIX_X4(r0, r1, r2, r3, addr)                                          \
    asm volatile("ldmatrix.sync.aligned.m8n8.x4.shared.b16 {%0,%1,%2,%3}, [%4];"   \
        : "=r"(r0), "=r"(r1), "=r"(r2), "=r"(r3) : "r"(addr))

#define MMA16816(c, a, b)                                                          \
    asm volatile("mma.sync.aligned.m16n8k16.row.col.f32.bf16.bf16.f32 "            \
        "{%0,%1,%2,%3}, {%4,%5,%6,%7}, {%8,%9}, {%0,%1,%2,%3};"                    \
        : "+f"((c)[0]), "+f"((c)[1]), "+f"((c)[2]), "+f"((c)[3])                   \
        : "r"((a)[0]), "r"((a)[1]), "r"((a)[2]), "r"((a)[3]),                      \
          "r"((b)[0]), "r"((b)[1]))

#define EX2(d, s) asm("ex2.approx.f32 %0, %1;" : "=f"(d) : "f"(s))

// ---------------------------------------------------------------------------
// Kernel W: weights -> bf16. q rows (0-31) pre-scaled by log2(e) so the
// fused kernel's softmax exp is a single ex2.
// ---------------------------------------------------------------------------
__global__ __launch_bounds__(256) void wconv_kernel(
    const float* __restrict__ wq, const float* __restrict__ bq,
    const float* __restrict__ wk, const float* __restrict__ bk,
    const float* __restrict__ wv, const float* __restrict__ bv)
{
    const int row = blockIdx.x;
    const int t = threadIdx.x;
    const float* src = row < 32 ? wq + row * CC_
                     : row < 64 ? wk + (row - 32) * CC_
                                : wv + (row - 64) * CC_;
    const float scale = row < 32 ? 1.4426950408889634f : 1.0f;
    g_w16[row][t] = __float2bfloat16(src[t] * scale);
    if (t == 0)
        g_biasf[row] = scale * (row < 32 ? bq[row]
                              : row < 64 ? bk[row - 32] : bv[row - 64]);
}

// ---------------------------------------------------------------------------
// Kernel A (HMMA QKV): unchanged from R7.
// ---------------------------------------------------------------------------
#define WROW    528
#define WS_OFF  0
#define XROW    144
#define XS_OFF  168960
#define BI_OFF  (168960 + 18432)
#define SMEM_Q  (168960 + 18432 + 1280)

__global__ __launch_bounds__(256, 1) void qkv_hmma_kernel(
    const float* __restrict__ x)
{
    extern __shared__ char smq[];
    const uint32_t sb = smem_u32(smq);
    const int tid  = threadIdx.x;
    const int wid  = tid >> 5;
    const int lane = tid & 31;
    const int b  = blockIdx.y;
    const int n0 = blockIdx.x * 128;

#pragma unroll
    for (int p = 0; p < 40; p++) {
        int idx = tid + p * 256;
        int row = idx >> 5, seg = idx & 31;
        CP_ASYNC16(sb + WS_OFF + row * WROW + seg * 16, &g_w16[row][seg * 8]);
    }
    if (tid < 80) CP_ASYNC16(sb + BI_OFF + tid * 16, &g_biasf[tid * 4]);
    CP_COMMIT();

    float accQ[8][4];
    float accV[4][8][4];
#pragma unroll
    for (int nt = 0; nt < 8; nt++)
#pragma unroll
        for (int r = 0; r < 4; r++) accQ[nt][r] = 0.f;
#pragma unroll
    for (int mt = 0; mt < 4; mt++)
#pragma unroll
        for (int nt = 0; nt < 8; nt++)
#pragma unroll
            for (int r = 0; r < 4; r++) accV[mt][nt][r] = 0.f;

    const int mw = wid >> 1;
    const int nw = wid & 1;
    const int ntok = tid & 127;
    const int cgrp = (tid >> 7) * 32;

    float xr[32];
    {
        const float* xp = x + ((size_t)(b * CC_ + cgrp)) * NN + n0 + ntok;
#pragma unroll
        for (int q = 0; q < 32; q++) xr[q] = xp[(size_t)q * NN];
    }

    for (int ck = 0; ck < 4; ck++) {
        __syncthreads();
#pragma unroll
        for (int q = 0; q < 16; q++) {
            __nv_bfloat162 pk = __floats2bfloat162_rn(xr[2 * q], xr[2 * q + 1]);
            *(uint32_t*)(smq + XS_OFF + ntok * XROW + (cgrp + 2 * q) * 2) =
                *(uint32_t*)&pk;
        }
        if (ck == 0) CP_WAIT0();
        __syncthreads();

        if (ck < 3) {
            const float* xp = x + ((size_t)(b * CC_ + (ck + 1) * 64 + cgrp)) * NN
                            + n0 + ntok;
#pragma unroll
            for (int q = 0; q < 32; q++) xr[q] = xp[(size_t)q * NN];
        }

        const uint32_t wbase = sb + WS_OFF + ck * 128;
#pragma unroll
        for (int ks = 0; ks < 4; ks++) {
            const int kb = ks * 32;
            uint32_t ax[4];
            {
                uint32_t addr = sb + XS_OFF + (wid * 16 + (lane & 15)) * XROW
                              + kb + ((lane >> 4) << 4);
                LDMATRIX_X4(ax[0], ax[1], ax[2], ax[3], addr);
            }
            uint32_t bw[8][2];
#pragma unroll
            for (int bt = 0; bt < 4; bt++) {
                int row = bt * 16 + ((lane >> 4) << 3) + (lane & 7);
                uint32_t addr = wbase + row * WROW + kb + (((lane >> 3) & 1) << 4);
                uint32_t r0, r1, r2, r3;
                LDMATRIX_X4(r0, r1, r2, r3, addr);
                bw[bt * 2 + 0][0] = r0; bw[bt * 2 + 0][1] = r1;
                bw[bt * 2 + 1][0] = r2; bw[bt * 2 + 1][1] = r3;
            }
#pragma unroll
            for (int nt = 0; nt < 8; nt++) MMA16816(accQ[nt], ax, bw[nt]);

            uint32_t aw[4][4];
#pragma unroll
            for (int mt = 0; mt < 4; mt++) {
                uint32_t addr = wbase + (64 + mw * 64 + mt * 16 + (lane & 15)) * WROW
                              + kb + ((lane >> 4) << 4);
                LDMATRIX_X4(aw[mt][0], aw[mt][1], aw[mt][2], aw[mt][3], addr);
            }
            uint32_t bx[8][2];
#pragma unroll
            for (int bt = 0; bt < 4; bt++) {
                int row = nw * 64 + bt * 16 + ((lane >> 4) << 3) + (lane & 7);
                uint32_t addr = sb + XS_OFF + row * XROW + kb
                              + (((lane >> 3) & 1) << 4);
                uint32_t r0, r1, r2, r3;
                LDMATRIX_X4(r0, r1, r2, r3, addr);
                bx[bt * 2 + 0][0] = r0; bx[bt * 2 + 0][1] = r1;
                bx[bt * 2 + 1][0] = r2; bx[bt * 2 + 1][1] = r3;
            }
#pragma unroll
            for (int mt = 0; mt < 4; mt++)
#pragma unroll
                for (int nt = 0; nt < 8; nt++)
                    MMA16816(accV[mt][nt], aw[mt], bx[nt]);
        }
    }

    const float* biasS = (const float*)(smq + BI_OFF);

    {
        int rq = n0 + wid * 16 + (lane >> 2);
#pragma unroll
        for (int nt = 0; nt < 8; nt++) {
            int r = nt * 8 + (lane & 3) * 2;
            float b0 = biasS[r], b1 = biasS[r + 1];
            __nv_bfloat162 pA = __floats2bfloat162_rn(accQ[nt][0] + b0,
                                                      accQ[nt][1] + b1);
            __nv_bfloat162 pB = __floats2bfloat162_rn(accQ[nt][2] + b0,
                                                      accQ[nt][3] + b1);
            if (nt < 4) {
                *(uint32_t*)&g_qT[b][rq][r]     = *(uint32_t*)&pA;
                *(uint32_t*)&g_qT[b][rq + 8][r] = *(uint32_t*)&pB;
            } else {
                *(uint32_t*)&g_kT[b][rq][r - 32]     = *(uint32_t*)&pA;
                *(uint32_t*)&g_kT[b][rq + 8][r - 32] = *(uint32_t*)&pB;
            }
        }
    }

#pragma unroll
    for (int mt = 0; mt < 4; mt++) {
        int vr = mw * 64 + mt * 16 + (lane >> 2);
        float b0 = biasS[64 + vr], b1 = biasS[64 + vr + 8];
#pragma unroll
        for (int nt = 0; nt < 8; nt++) {
            int col = n0 + nw * 64 + nt * 8 + (lane & 3) * 2;
            __nv_bfloat162 pA = __floats2bfloat162_rn(accV[mt][nt][0] + b0,
                                                      accV[mt][nt][1] + b0);
            __nv_bfloat162 pB = __floats2bfloat162_rn(accV[mt][nt][2] + b1,
                                                      accV[mt][nt][3] + b1);
            *(uint32_t*)&g_v16[b][vr][col]     = *(uint32_t*)&pA;
            *(uint32_t*)&g_v16[b][vr + 8][col] = *(uint32_t*)&pB;
        }
    }
}

// ---------------------------------------------------------------------------
// Kernel F (fused flash attention, HMMA), R11: R9 tiling + triple buffer
// (one barrier/chunk, depth-2 prefetch) + ex2 softmax + interleaved PV mma.
// grid (32 i, 4 b) = 128 CTAs, 256 threads, 136192 B dyn smem.
// ---------------------------------------------------------------------------
#define QS_OFF   0
#define KC_OFF   10240
#define KC_BUF   5120
#define VC_OFF   (10240 + 3 * 5120)       // 25600
#define VC_BUF   36864
#define SMEM_F   (25600 + 3 * 36864)      // 136192

__global__ __launch_bounds__(256, 1) void fused_attn_kernel(
    const float* __restrict__ x, const float* __restrict__ gamma_p,
    float* __restrict__ out)
{
    extern __shared__ char smem[];
    const uint32_t sb = smem_u32(smem);
    const int tid  = threadIdx.x;
    const int wid  = tid >> 5;
    const int lane = tid & 31;
    const int b  = blockIdx.y;
    const int i0 = blockIdx.x * 128;
    const int mq = wid;

    auto load_chunk = [&](int chunk) {
        const int j0 = chunk * 64;
        const int buf = chunk % 3;
        {
            int row = tid >> 2, seg = tid & 3;
            CP_ASYNC16(sb + KC_OFF + buf * KC_BUF + row * 80 + seg * 16,
                       &g_kT[b][j0 + row][seg * 8]);
        }
#pragma unroll
        for (int p = 0; p < 8; p++) {
            int idx = tid + p * 256;
            int row = idx >> 3, seg = idx & 7;
            CP_ASYNC16(sb + VC_OFF + buf * VC_BUF + row * 144 + seg * 16,
                       &g_v16[b][row][j0 + seg * 8]);
        }
        CP_COMMIT();
    };

    // prologue: q tile rides group 0 with chunk 0; chunk 1 is group 1.
    {
#pragma unroll
        for (int p = 0; p < 2; p++) {
            int idx = tid + p * 256;
            int row = idx >> 2, seg = idx & 3;
            CP_ASYNC16(sb + QS_OFF + row * 80 + seg * 16, &g_qT[b][i0 + row][seg * 8]);
        }
    }
    load_chunk(0);
    load_chunk(1);

    float acc[32][4];
#pragma unroll
    for (int nt = 0; nt < 32; nt++)
#pragma unroll
        for (int r = 0; r < 4; r++) acc[nt][r] = 0.f;

    uint32_t qf[2][4];
    float sum0 = 0.f, sum1 = 0.f;

    for (int chunk = 0; chunk < NN / 64; chunk++) {
        if (chunk == NN / 64 - 1) CP_WAIT0(); else CP_WAIT1();
        __syncthreads();   // single barrier per chunk (triple buffer)
        if (chunk + 2 < NN / 64) load_chunk(chunk + 2);

        if (chunk == 0) {
#pragma unroll
            for (int ks = 0; ks < 2; ks++) {
                uint32_t addr = sb + QS_OFF + (mq * 16 + (lane & 15)) * 80
                              + ks * 32 + ((lane >> 4) << 4);
                LDMATRIX_X4(qf[ks][0], qf[ks][1], qf[ks][2], qf[ks][3], addr);
            }
        }

        // ---- S = q.k : per 16-row K group, interleaved cc pair ----
        const uint32_t kbuf = sb + KC_OFF + (chunk % 3) * KC_BUF;
        float cc[8][4];
#pragma unroll
        for (int nt = 0; nt < 8; nt++)
#pragma unroll
            for (int r = 0; r < 4; r++) cc[nt][r] = 0.f;

#pragma unroll
        for (int bt = 0; bt < 4; bt++) {
            const int row = bt * 16 + ((lane >> 4) << 3) + (lane & 7);
            uint32_t k0[4], k1[4];
            LDMATRIX_X4(k0[0], k0[1], k0[2], k0[3],
                        kbuf + row * 80 + (((lane >> 3) & 1) << 4));
            LDMATRIX_X4(k1[0], k1[1], k1[2], k1[3],
                        kbuf + row * 80 + 32 + (((lane >> 3) & 1) << 4));
            uint32_t bfr[2];
            bfr[0] = k0[0]; bfr[1] = k0[1]; MMA16816(cc[bt * 2 + 0], qf[0], bfr);
            bfr[0] = k0[2]; bfr[1] = k0[3]; MMA16816(cc[bt * 2 + 1], qf[0], bfr);
            bfr[0] = k1[0]; bfr[1] = k1[1]; MMA16816(cc[bt * 2 + 0], qf[1], bfr);
            bfr[0] = k1[2]; bfr[1] = k1[3]; MMA16816(cc[bt * 2 + 1], qf[1], bfr);
        }

        // ---- exp2 (log2e pre-folded into q) + rowsum + repack -> A-frags ----
        uint32_t aP[4][4];
#pragma unroll
        for (int nt = 0; nt < 8; nt++) {
            float e0, e1, e2, e3;
            EX2(e0, cc[nt][0]);
            EX2(e1, cc[nt][1]);
            EX2(e2, cc[nt][2]);
            EX2(e3, cc[nt][3]);
            sum0 += e0 + e1;
            sum1 += e2 + e3;
            __nv_bfloat162 pA = __floats2bfloat162_rn(e0, e1);
            __nv_bfloat162 pB = __floats2bfloat162_rn(e2, e3);
            int kk = nt >> 1;
            if ((nt & 1) == 0) { aP[kk][0] = *(uint32_t*)&pA; aP[kk][1] = *(uint32_t*)&pB; }
            else               { aP[kk][2] = *(uint32_t*)&pA; aP[kk][3] = *(uint32_t*)&pB; }
        }

        // ---- acc += P'@V : interleave acc pair per fragment ----
        const uint32_t vbuf = sb + VC_OFF + (chunk % 3) * VC_BUF;
#pragma unroll
        for (int bt = 0; bt < 16; bt++) {
            const int row = bt * 16 + ((lane >> 4) << 3) + (lane & 7);
            const uint32_t raddr = vbuf + row * 144 + (((lane >> 3) & 1) << 4);
            uint32_t v0[4], v1[4], v2[4], v3[4];
            LDMATRIX_X4(v0[0], v0[1], v0[2], v0[3], raddr);
            LDMATRIX_X4(v1[0], v1[1], v1[2], v1[3], raddr + 32);
            LDMATRIX_X4(v2[0], v2[1], v2[2], v2[3], raddr + 64);
            LDMATRIX_X4(v3[0], v3[1], v3[2], v3[3], raddr + 96);
            uint32_t bfr[2];
            bfr[0] = v0[0]; bfr[1] = v0[1]; MMA16816(acc[bt * 2 + 0], aP[0], bfr);
            bfr[0] = v0[2]; bfr[1] = v0[3]; MMA16816(acc[bt * 2 + 1], aP[0], bfr);
            bfr[0] = v1[0]; bfr[1] = v1[1]; MMA16816(acc[bt * 2 + 0], aP[1], bfr);
            bfr[0] = v1[2]; bfr[1] = v1[3]; MMA16816(acc[bt * 2 + 1], aP[1], bfr);
            bfr[0] = v2[0]; bfr[1] = v2[1]; MMA16816(acc[bt * 2 + 0], aP[2], bfr);
            bfr[0] = v2[2]; bfr[1] = v2[3]; MMA16816(acc[bt * 2 + 1], aP[2], bfr);
            bfr[0] = v3[0]; bfr[1] = v3[1]; MMA16816(acc[bt * 2 + 0], aP[3], bfr);
            bfr[0] = v3[2]; bfr[1] = v3[3]; MMA16816(acc[bt * 2 + 1], aP[3], bfr);
        }
    }

    sum0 += __shfl_xor_sync(0xffffffffu, sum0, 1);
    sum0 += __shfl_xor_sync(0xffffffffu, sum0, 2);
    sum1 += __shfl_xor_sync(0xffffffffu, sum1, 1);
    sum1 += __shfl_xor_sync(0xffffffffu, sum1, 2);
    const float gam = gamma_p[0];
    const float ig0 = gam / sum0;
    const float ig1 = gam / sum1;

    const int g2 = lane >> 2;
    const int tg = lane & 3;
    const int irow = i0 + mq * 16 + g2;
#pragma unroll
    for (int nt = 0; nt < 32; nt++) {
        int c = nt * 8 + tg * 2;
        size_t o00 = ((size_t)(b * CC_ + c)) * NN + irow;
        size_t o10 = o00 + NN;
        out[o00]     = fmaf(ig0, acc[nt][0], x[o00]);
        out[o10]     = fmaf(ig0, acc[nt][1], x[o10]);
        out[o00 + 8] = fmaf(ig1, acc[nt][2], x[o00 + 8]);
        out[o10 + 8] = fmaf(ig1, acc[nt][3], x[o10 + 8]);
    }
}

// ---------------------------------------------------------------------------
extern "C" void kernel_launch(void* const* d_in, const int* in_sizes, int n_in,
                              void* d_out, int out_size)
{
    const float* x     = (const float*)d_in[0];
    const float* wq    = (const float*)d_in[1];
    const float* bq    = (const float*)d_in[2];
    const float* wk    = (const float*)d_in[3];
    const float* bk    = (const float*)d_in[4];
    const float* wv    = (const float*)d_in[5];
    const float* bv    = (const float*)d_in[6];
    const float* gamma = (const float*)d_in[7];
    float* out = (float*)d_out;

    cudaFuncSetAttribute(qkv_hmma_kernel,
                         cudaFuncAttributeMaxDynamicSharedMemorySize, SMEM_Q);
    cudaFuncSetAttribute(fused_attn_kernel,
                         cudaFuncAttributeMaxDynamicSharedMemorySize, SMEM_F);

    wconv_kernel<<<dim3(320), 256>>>(wq, bq, wk, bk, wv, bv);
    qkv_hmma_kernel<<<dim3(32, 4), 256, SMEM_Q>>>(x);
    fused_attn_kernel<<<dim3(32, 4), 256, SMEM_F>>>(x, gamma, out);
}